// round 12
// baseline (speedup 1.0000x reference)
#include <cuda_runtime.h>
#include <math.h>

#define VOCAB  8000
#define MAXDEC 50
#define NSTEPS 49
#define SENTINEL 7777   // diagnostic: all-NaN logits -> constant 7777 -> rel_err ~0.959

// ---------------- scratch layout (floats) ----------------
#define OFF_PATCH    0ull            // 8192*1280
#define OFF_C1       10485760ull     // 8192*512
#define OFF_C2       14680064ull     // 4096*512
#define OFF_XTBC     16777216ull     // 4096*512
#define OFF_GIF      18874368ull     // 4096*1536
#define OFF_GIB      25165824ull     // 4096*1536
#define OFF_ENCOUT   31457280ull     // 32*128*1024
#define OFF_ENCPROJ  35651584ull     // 32*128*512
#define OFF_HBUF     37748736ull     // 2*2*32*512 (parity, dir, b, j)
#define OFF_COMB     37814272ull     // 32*1024
#define OFF_BRIDGE   37847040ull     // 32*1024
#define OFF_H0BUF    37879808ull     // 2*32*512 (parity ping-pong)
#define OFF_H1BUF    37912576ull     // 2*32*512
#define OFF_CTX      37945344ull     // 32*1024
#define OFF_LOGITS   37978112ull     // 32*8000
#define OFF_TOK      38234112ull     // 32 ints
#define SCRATCH_FLOATS 38234176ull

static __device__ float g_scratch[SCRATCH_FLOATS];

// ---------------- standalone GEMM: C[M,N] = act(A[M,K].B[N,K]^T + bias) ------
__global__ void gemm_abt(const float* __restrict__ A, const float* __restrict__ Bm,
                         const float* __restrict__ bias, float* __restrict__ C,
                         int M, int N, int K, int relu)
{
    __shared__ float As[16][65];
    __shared__ float Bs[16][65];
    int tid = threadIdx.x;
    int tx = tid & 15, ty = tid >> 4;
    int m0 = blockIdx.x * 64, n0 = blockIdx.y * 64;
    float acc[4][4];
#pragma unroll
    for (int i = 0; i < 4; i++)
#pragma unroll
        for (int j = 0; j < 4; j++) acc[i][j] = 0.f;

    for (int k0 = 0; k0 < K; k0 += 16) {
#pragma unroll
        for (int r = 0; r < 4; r++) {
            int i  = tid + r * 256;
            int mm = i >> 4, kk = i & 15;
            As[kk][mm] = (m0 + mm < M) ? A[(size_t)(m0 + mm) * K + k0 + kk] : 0.f;
            Bs[kk][mm] = (n0 + mm < N) ? Bm[(size_t)(n0 + mm) * K + k0 + kk] : 0.f;
        }
        __syncthreads();
#pragma unroll
        for (int kk = 0; kk < 16; kk++) {
            float a[4], b[4];
#pragma unroll
            for (int i = 0; i < 4; i++) a[i] = As[kk][ty * 4 + i];
#pragma unroll
            for (int j = 0; j < 4; j++) b[j] = Bs[kk][tx * 4 + j];
#pragma unroll
            for (int i = 0; i < 4; i++)
#pragma unroll
                for (int j = 0; j < 4; j++) acc[i][j] = fmaf(a[i], b[j], acc[i][j]);
        }
        __syncthreads();
    }
#pragma unroll
    for (int i = 0; i < 4; i++) {
        int m = m0 + ty * 4 + i;
        if (m >= M) continue;
#pragma unroll
        for (int j = 0; j < 4; j++) {
            int n = n0 + tx * 4 + j;
            if (n >= N) continue;
            float v = acc[i][j] + (bias ? bias[n] : 0.f);
            if (relu) v = fmaxf(v, 0.f);
            C[(size_t)m * N + n] = v;
        }
    }
}

// ---------------- conv im2col / transpose ----------------
__global__ void im2col1(const float* __restrict__ f, float* __restrict__ patch)
{
    long long idx = (long long)blockIdx.x * 256 + threadIdx.x;
    if (idx >= 8192LL * 1280) return;
    int col = (int)(idx % 1280);
    int row = (int)(idx / 1280);
    int ol = row & 255, b = row >> 8;
    int ic = col / 5, kk = col % 5;
    int l = 2 * ol - 2 + kk;
    patch[idx] = (l >= 0 && l < 512) ? f[((size_t)b * 512 + l) * 256 + ic] : 0.f;
}

__global__ void im2col2(const float* __restrict__ c1, float* __restrict__ patch)
{
    long long idx = (long long)blockIdx.x * 256 + threadIdx.x;
    if (idx >= 4096LL * 2560) return;
    int col = (int)(idx % 2560);
    int row = (int)(idx / 2560);
    int ol = row & 127, b = row >> 7;
    int ic = col / 5, kk = col % 5;
    int l = 2 * ol - 2 + kk;
    patch[idx] = (l >= 0 && l < 256) ? c1[((size_t)b * 256 + l) * 512 + ic] : 0.f;
}

__global__ void xpose_bt(const float* __restrict__ c2, float* __restrict__ xtbc)
{
    int idx = blockIdx.x * 256 + threadIdx.x;
    if (idx >= 4096 * 512) return;
    int c = idx & 511;
    int row = idx >> 9;
    int t = row >> 5, b = row & 31;
    xtbc[idx] = c2[((size_t)b * 128 + t) * 512 + c];
}

// ---------------- encoder step: one launch per timestep ----------------------
__global__ void enc_step_k(const float* __restrict__ gif, const float* __restrict__ gib,
                           const float* __restrict__ WhhF, const float* __restrict__ WhhB,
                           const float* __restrict__ bhhF, const float* __restrict__ bhhB,
                           float* __restrict__ encout, float* __restrict__ hbuf, int t)
{
    __shared__ float As[32][17];
    __shared__ float Bs[3][32][17];
    const int tid = threadIdx.x;
    const int dir = blockIdx.x >> 4;
    const int j0  = (blockIdx.x & 15) * 32;
    const float* Whh = dir ? WhhB : WhhF;
    const float* bhh = dir ? bhhB : bhhF;
    const float* giB = dir ? gib : gif;
    const int tx = tid & 31;
    const int ty = tid >> 5;
    const int j  = j0 + tx;

    const float* hin  = hbuf + (t & 1) * 32768 + dir * 16384;
    float*       hout = hbuf + ((t + 1) & 1) * 32768 + dir * 16384;

    float acc[3][4] = {{0,0,0,0},{0,0,0,0},{0,0,0,0}};

    for (int k0 = 0; k0 < 512; k0 += 16) {
        {
            int m = tid >> 4, kk = tid & 15;
            As[m][kk] = hin[m * 512 + k0 + kk];
            int e = tid + 256; m = e >> 4; kk = e & 15;
            As[m][kk] = hin[m * 512 + k0 + kk];
        }
#pragma unroll
        for (int i = 0; i < 6; i++) {
            int e = tid + i * 256;
            int g = e >> 9, rest = e & 511;
            int n = rest >> 4, kk = rest & 15;
            Bs[g][n][kk] = Whh[(size_t)(g * 512 + j0 + n) * 512 + k0 + kk];
        }
        __syncthreads();
#pragma unroll
        for (int kk = 0; kk < 16; kk++) {
            float b0 = Bs[0][tx][kk], b1 = Bs[1][tx][kk], b2 = Bs[2][tx][kk];
#pragma unroll
            for (int r = 0; r < 4; r++) {
                float a = As[ty * 4 + r][kk];
                acc[0][r] = fmaf(a, b0, acc[0][r]);
                acc[1][r] = fmaf(a, b1, acc[1][r]);
                acc[2][r] = fmaf(a, b2, acc[2][r]);
            }
        }
        __syncthreads();
    }

    const int ts = dir ? (127 - t) : t;
    const float* gi = giB + (size_t)ts * 32 * 1536;
    const float b_r = bhh[j], b_z = bhh[512 + j], b_n = bhh[1024 + j];
#pragma unroll
    for (int r = 0; r < 4; r++) {
        int m = ty * 4 + r;
        float ir = gi[m * 1536 + j], iz = gi[m * 1536 + 512 + j], in = gi[m * 1536 + 1024 + j];
        float rr = 1.f / (1.f + expf(-(ir + acc[0][r] + b_r)));
        float zz = 1.f / (1.f + expf(-(iz + acc[1][r] + b_z)));
        float nn = tanhf(in + rr * (acc[2][r] + b_n));
        float hv = (1.f - zz) * nn + zz * hin[m * 512 + j];
        hout[m * 512 + j] = hv;
        encout[((size_t)m * 128 + ts) * 1024 + dir * 512 + j] = hv;
    }
}

__global__ void build_comb_k(const float* __restrict__ hbuf, float* __restrict__ comb)
{
    int i = blockIdx.x * 256 + threadIdx.x;
    if (i >= 32 * 1024) return;
    int b = i >> 10, jj = i & 1023;
    comb[i] = (jj < 512) ? hbuf[b * 512 + jj] : hbuf[16384 + b * 512 + (jj - 512)];
}

__global__ void split_bridge_k(const float* __restrict__ br, float* __restrict__ h0,
                               float* __restrict__ h1)
{
    int i = blockIdx.x * 256 + threadIdx.x;
    if (i >= 32 * 512) return;
    int b = i >> 9, j = i & 511;
    h0[i] = br[b * 1024 + j];
    h1[i] = br[b * 1024 + 512 + j];
}

// out is FLOAT32 (the harness's __output__ dtype): tokens stored as floats.
__global__ void init_dec_k(int* __restrict__ tok, float* __restrict__ out)
{
    int b = threadIdx.x;   // 32
    tok[b] = 1;            // SOS
    out[b * MAXDEC] = 1.0f;
}

// ---------------- decoder: fused attention (dq computed in-block) ------------
__global__ void dec_attn_k(const float* __restrict__ encproj, const float* __restrict__ encout,
                           const float* __restrict__ h1, const float* __restrict__ Wd,
                           const float* __restrict__ v, float* __restrict__ ctx)
{
    int b = blockIdx.x;
    int tid = threadIdx.x;
    int lane = tid & 31, warp = tid >> 5;
    __shared__ float s_h[512];
    __shared__ float s_dq[512];
    __shared__ float s_sc[128];
    __shared__ float s_red[256];

    for (int i = tid; i < 512; i += 256) s_h[i] = h1[b * 512 + i];
    __syncthreads();

    for (int a = warp; a < 512; a += 8) {
        const float* wr = Wd + (size_t)a * 512;
        float acc = 0.f;
        for (int k = lane; k < 512; k += 32) acc = fmaf(s_h[k], wr[k], acc);
#pragma unroll
        for (int o = 16; o; o >>= 1) acc += __shfl_xor_sync(0xffffffffu, acc, o);
        if (lane == 0) s_dq[a] = acc;
    }
    __syncthreads();

    for (int t = warp; t < 128; t += 8) {
        const float* ep = encproj + ((size_t)b * 128 + t) * 512;
        float acc = 0.f;
        for (int a = lane; a < 512; a += 32)
            acc = fmaf(tanhf(ep[a] + s_dq[a]), v[a], acc);
#pragma unroll
        for (int o = 16; o; o >>= 1) acc += __shfl_xor_sync(0xffffffffu, acc, o);
        if (lane == 0) s_sc[t] = acc;
    }
    __syncthreads();

    float mv = (tid < 128) ? s_sc[tid] : -INFINITY;
    s_red[tid] = mv; __syncthreads();
    for (int o = 128; o; o >>= 1) {
        if (tid < o) s_red[tid] = fmaxf(s_red[tid], s_red[tid + o]);
        __syncthreads();
    }
    float mx = s_red[0]; __syncthreads();
    float ev = (tid < 128) ? expf(s_sc[tid] - mx) : 0.f;
    s_red[tid] = ev; __syncthreads();
    for (int o = 128; o; o >>= 1) {
        if (tid < o) s_red[tid] += s_red[tid + o];
        __syncthreads();
    }
    float dn = s_red[0]; __syncthreads();
    if (tid < 128) s_sc[tid] = ev / dn;
    __syncthreads();

    for (int j = tid; j < 1024; j += 256) {
        const float* eo = encout + (size_t)b * 131072 + j;
        float acc = 0.f;
#pragma unroll 4
        for (int t = 0; t < 128; t++) acc = fmaf(s_sc[t], eo[(size_t)t * 1024], acc);
        ctx[b * 1024 + j] = acc;
    }
}

// ---------------- decoder: fused layer-0 gates + GRU update ------------------
__global__ void dec_gates0_k(const float* __restrict__ emb, const int* __restrict__ tok,
                             const float* __restrict__ ctx, const float* __restrict__ hin,
                             const float* __restrict__ Wih, const float* __restrict__ Whh,
                             const float* __restrict__ bih, const float* __restrict__ bhh,
                             float* __restrict__ hout)
{
    __shared__ float As[32][17];
    __shared__ float Bs[64][17];
    __shared__ float sacc[32][65];
    const int tid = threadIdx.x;
    const int j0 = blockIdx.x * 16;
    const int tx = tid & 15, ty = tid >> 4;
    const int KX = 1536, KTOT = 2048;
    float acc[2][4] = {{0,0,0,0},{0,0,0,0}};

    for (int k0 = 0; k0 < KTOT; k0 += 16) {
#pragma unroll
        for (int rep = 0; rep < 2; rep++) {
            int e = tid + rep * 256;
            int m = e >> 4, kk = e & 15;
            int k = k0 + kk;
            float av;
            if (k < 512) {
                int tk = tok[m];
                if (tk < 0) tk = 0;
                if (tk >= VOCAB) tk = VOCAB - 1;   // defensive clamp
                av = emb[(size_t)tk * 512 + k];
            }
            else if (k < 1536) av = ctx[m * 1024 + (k - 512)];
            else               av = hin[m * 512 + (k - 1536)];
            As[m][kk] = av;
        }
#pragma unroll
        for (int i = 0; i < 4; i++) {
            int e = tid + i * 256;
            int c = e >> 4, kk = e & 15;
            int k = k0 + kk;
            int g = c >> 4, jj = c & 15;
            float bv;
            if (g < 2) {
                int row = g * 512 + j0 + jj;
                bv = (k < KX) ? Wih[(size_t)row * KX + k] : Whh[(size_t)row * 512 + (k - KX)];
            } else if (g == 2) {
                int row = 1024 + j0 + jj;
                bv = (k < KX) ? Wih[(size_t)row * KX + k] : 0.f;
            } else {
                int row = 1024 + j0 + jj;
                bv = (k >= KX) ? Whh[(size_t)row * 512 + (k - KX)] : 0.f;
            }
            Bs[c][kk] = bv;
        }
        __syncthreads();
#pragma unroll
        for (int kk = 0; kk < 16; kk++) {
            float a0 = As[ty * 2][kk], a1 = As[ty * 2 + 1][kk];
#pragma unroll
            for (int cc = 0; cc < 4; cc++) {
                float bv = Bs[tx * 4 + cc][kk];
                acc[0][cc] = fmaf(a0, bv, acc[0][cc]);
                acc[1][cc] = fmaf(a1, bv, acc[1][cc]);
            }
        }
        __syncthreads();
    }
#pragma unroll
    for (int cc = 0; cc < 4; cc++) {
        sacc[ty * 2][tx * 4 + cc]     = acc[0][cc];
        sacc[ty * 2 + 1][tx * 4 + cc] = acc[1][cc];
    }
    __syncthreads();

    for (int i = tid; i < 512; i += 256) {
        int b = i >> 4, jj = i & 15;
        int j = j0 + jj;
        float r_  = sacc[b][jj]      + bih[j]        + bhh[j];
        float z_  = sacc[b][16 + jj] + bih[512 + j]  + bhh[512 + j];
        float in_ = sacc[b][32 + jj] + bih[1024 + j];
        float hn_ = sacc[b][48 + jj] + bhh[1024 + j];
        float rr = 1.f / (1.f + expf(-r_));
        float zz = 1.f / (1.f + expf(-z_));
        float nn = tanhf(in_ + rr * hn_);
        hout[b * 512 + j] = (1.f - zz) * nn + zz * hin[b * 512 + j];
    }
}

// ---------------- decoder: fused layer-1 gates (A = [h0new | h1old], K=1024) --
__global__ void dec_gates1_k(const float* __restrict__ x,
                             const float* __restrict__ hin,
                             const float* __restrict__ Wih, const float* __restrict__ Whh,
                             const float* __restrict__ bih, const float* __restrict__ bhh,
                             float* __restrict__ hout)
{
    __shared__ float As[32][17];
    __shared__ float Bs[64][17];
    __shared__ float sacc[32][65];
    const int tid = threadIdx.x;
    const int j0 = blockIdx.x * 16;
    const int tx = tid & 15, ty = tid >> 4;
    const int KX = 512, KTOT = 1024;
    float acc[2][4] = {{0,0,0,0},{0,0,0,0}};

    for (int k0 = 0; k0 < KTOT; k0 += 16) {
#pragma unroll
        for (int rep = 0; rep < 2; rep++) {
            int e = tid + rep * 256;
            int m = e >> 4, kk = e & 15;
            int k = k0 + kk;
            As[m][kk] = (k < 512) ? x[m * 512 + k] : hin[m * 512 + (k - 512)];
        }
#pragma unroll
        for (int i = 0; i < 4; i++) {
            int e = tid + i * 256;
            int c = e >> 4, kk = e & 15;
            int k = k0 + kk;
            int g = c >> 4, jj = c & 15;
            float bv;
            if (g < 2) {
                int row = g * 512 + j0 + jj;
                bv = (k < KX) ? Wih[(size_t)row * KX + k] : Whh[(size_t)row * 512 + (k - KX)];
            } else if (g == 2) {
                int row = 1024 + j0 + jj;
                bv = (k < KX) ? Wih[(size_t)row * KX + k] : 0.f;
            } else {
                int row = 1024 + j0 + jj;
                bv = (k >= KX) ? Whh[(size_t)row * 512 + (k - KX)] : 0.f;
            }
            Bs[c][kk] = bv;
        }
        __syncthreads();
#pragma unroll
        for (int kk = 0; kk < 16; kk++) {
            float a0 = As[ty * 2][kk], a1 = As[ty * 2 + 1][kk];
#pragma unroll
            for (int cc = 0; cc < 4; cc++) {
                float bv = Bs[tx * 4 + cc][kk];
                acc[0][cc] = fmaf(a0, bv, acc[0][cc]);
                acc[1][cc] = fmaf(a1, bv, acc[1][cc]);
            }
        }
        __syncthreads();
    }
#pragma unroll
    for (int cc = 0; cc < 4; cc++) {
        sacc[ty * 2][tx * 4 + cc]     = acc[0][cc];
        sacc[ty * 2 + 1][tx * 4 + cc] = acc[1][cc];
    }
    __syncthreads();

    for (int i = tid; i < 512; i += 256) {
        int b = i >> 4, jj = i & 15;
        int j = j0 + jj;
        float r_  = sacc[b][jj]      + bih[j]        + bhh[j];
        float z_  = sacc[b][16 + jj] + bih[512 + j]  + bhh[512 + j];
        float in_ = sacc[b][32 + jj] + bih[1024 + j];
        float hn_ = sacc[b][48 + jj] + bhh[1024 + j];
        float rr = 1.f / (1.f + expf(-r_));
        float zz = 1.f / (1.f + expf(-z_));
        float nn = tanhf(in_ + rr * hn_);
        hout[b * 512 + j] = (1.f - zz) * nn + zz * hin[b * 512 + j];
    }
}

// ---------------- decoder: logits GEMM with [h1|ctx] gathered A --------------
__global__ void dec_logits_k(const float* __restrict__ h1, const float* __restrict__ ctx,
                             const float* __restrict__ Bm, const float* __restrict__ bias,
                             float* __restrict__ C)
{
    __shared__ float As[16][65];
    __shared__ float Bs[16][65];
    const int tid = threadIdx.x;
    const int tx = tid & 15, ty = tid >> 4;
    const int n0 = blockIdx.x * 64;
    const int K = 1536;
    float acc[4][4];
#pragma unroll
    for (int i = 0; i < 4; i++)
#pragma unroll
        for (int j = 0; j < 4; j++) acc[i][j] = 0.f;

    for (int k0 = 0; k0 < K; k0 += 16) {
#pragma unroll
        for (int r = 0; r < 4; r++) {
            int i  = tid + r * 256;
            int mm = i >> 4, kk = i & 15;
            int k = k0 + kk;
            float av = 0.f;
            if (mm < 32)
                av = (k < 512) ? h1[mm * 512 + k] : ctx[mm * 1024 + (k - 512)];
            As[kk][mm] = av;
            Bs[kk][mm] = Bm[(size_t)(n0 + mm) * K + k];
        }
        __syncthreads();
#pragma unroll
        for (int kk = 0; kk < 16; kk++) {
            float a[4], b[4];
#pragma unroll
            for (int i = 0; i < 4; i++) a[i] = As[kk][ty * 4 + i];
#pragma unroll
            for (int j = 0; j < 4; j++) b[j] = Bs[kk][tx * 4 + j];
#pragma unroll
            for (int i = 0; i < 4; i++)
#pragma unroll
                for (int j = 0; j < 4; j++) acc[i][j] = fmaf(a[i], b[j], acc[i][j]);
        }
        __syncthreads();
    }
#pragma unroll
    for (int i = 0; i < 4; i++) {
        int m = ty * 4 + i;
        if (m >= 32) continue;
#pragma unroll
        for (int j = 0; j < 4; j++) {
            int n = n0 + tx * 4 + j;
            C[(size_t)m * VOCAB + n] = acc[i][j] + bias[n];
        }
    }
}

// out is FLOAT32: token index stored as float value.
__global__ void argmax_k(const float* __restrict__ logits, int* __restrict__ tok,
                         float* __restrict__ out, int s)
{
    int b = blockIdx.x;
    int tid = threadIdx.x;
    float best = -INFINITY; int bi = SENTINEL;
    for (int i = tid; i < VOCAB; i += 256) {
        float v = logits[(size_t)b * VOCAB + i];
        if (v > best) { best = v; bi = i; }
    }
    __shared__ float sv[256];
    __shared__ int   si[256];
    sv[tid] = best; si[tid] = bi; __syncthreads();
    for (int o = 128; o; o >>= 1) {
        if (tid < o) {
            if (sv[tid + o] > sv[tid] || (sv[tid + o] == sv[tid] && si[tid + o] < si[tid])) {
                sv[tid] = sv[tid + o]; si[tid] = si[tid + o];
            }
        }
        __syncthreads();
    }
    if (tid == 0) { tok[b] = si[0]; out[b * MAXDEC + s + 1] = (float)si[0]; }
}

// ---------------- host ----------------
static inline unsigned cdiv(unsigned a, unsigned b) { return (a + b - 1) / b; }

static void gemm(const float* A, const float* Bm, const float* bias, float* C,
                 int M, int N, int K, int relu)
{
    dim3 grid(cdiv(M, 64), cdiv(N, 64));
    gemm_abt<<<grid, 256>>>(A, Bm, bias, C, M, N, K, relu);
}

// logical input ids
enum {
    I_FEAT, I_CW1, I_CB1, I_CW2, I_CB2,
    I_EWIHF, I_EWHHF, I_EBIHF, I_EBHHF,
    I_EWIHB, I_EWHHB, I_EBIHB, I_EBHHB,
    I_BRW, I_BRB, I_EMB, I_AWE, I_AWD, I_AV,
    I_DWIH0, I_DWHH0, I_DBIH0, I_DBHH0,
    I_DWIH1, I_DWHH1, I_DBIH1, I_DBHH1,
    I_PW, I_PB, N_LOGICAL
};

extern "C" void kernel_launch(void* const* d_in, const int* in_sizes, int n_in,
                              void* d_out, int out_size)
{
    (void)out_size;
    // Candidate A: reference-signature / dict-insertion order.
    static const int posA[N_LOGICAL] = {
        0, 1, 2, 3, 4,  5, 6, 7, 8,  9, 10, 11, 12,
        13, 14, 15, 16, 17, 18,  19, 20, 21, 22,  23, 24, 25, 26,  27, 28 };
    // Candidate B: sorted-key order (ASCII, uppercase < lowercase).
    static const int posB[N_LOGICAL] = {
        26, 7, 5, 8, 6,  21, 19, 25, 23,  20, 18, 24, 22,
        3, 4, 17, 1, 0, 2,  11, 9, 15, 13,  12, 10, 16, 14,  27, 28 };
    // expected element counts per logical input
    static const long long esz[N_LOGICAL] = {
        4194304, 655360, 512, 1310720, 512,
        786432, 786432, 1536, 1536,  786432, 786432, 1536, 1536,
        1048576, 1024, 4096000, 524288, 262144, 512,
        2359296, 786432, 1536, 1536,  786432, 786432, 1536, 1536,
        12288000, 8000 };

    const int* pos = posA;
    if (n_in >= N_LOGICAL && in_sizes) {
        int misB = 0;
        for (int i = 0; i < N_LOGICAL; i++)
            if ((long long)in_sizes[posB[i]] != esz[i]) misB++;
        if (misB == 0) {
            int misA = 0;
            for (int i = 0; i < N_LOGICAL; i++)
                if ((long long)in_sizes[posA[i]] != esz[i]) misA++;
            if (misA > 0) pos = posB;   // B matches exactly, A doesn't
        }
    }

    const float* features = (const float*)d_in[pos[I_FEAT]];
    const float* conv_w1  = (const float*)d_in[pos[I_CW1]];
    const float* conv_b1  = (const float*)d_in[pos[I_CB1]];
    const float* conv_w2  = (const float*)d_in[pos[I_CW2]];
    const float* conv_b2  = (const float*)d_in[pos[I_CB2]];
    const float* Wih_f    = (const float*)d_in[pos[I_EWIHF]];
    const float* Whh_f    = (const float*)d_in[pos[I_EWHHF]];
    const float* bih_f    = (const float*)d_in[pos[I_EBIHF]];
    const float* bhh_f    = (const float*)d_in[pos[I_EBHHF]];
    const float* Wih_b    = (const float*)d_in[pos[I_EWIHB]];
    const float* Whh_b    = (const float*)d_in[pos[I_EWHHB]];
    const float* bih_b    = (const float*)d_in[pos[I_EBIHB]];
    const float* bhh_b    = (const float*)d_in[pos[I_EBHHB]];
    const float* bridge_W = (const float*)d_in[pos[I_BRW]];
    const float* bridge_b = (const float*)d_in[pos[I_BRB]];
    const float* emb      = (const float*)d_in[pos[I_EMB]];
    const float* attn_We  = (const float*)d_in[pos[I_AWE]];
    const float* attn_Wd  = (const float*)d_in[pos[I_AWD]];
    const float* attn_v   = (const float*)d_in[pos[I_AV]];
    const float* dWih0    = (const float*)d_in[pos[I_DWIH0]];
    const float* dWhh0    = (const float*)d_in[pos[I_DWHH0]];
    const float* dbih0    = (const float*)d_in[pos[I_DBIH0]];
    const float* dbhh0    = (const float*)d_in[pos[I_DBHH0]];
    const float* dWih1    = (const float*)d_in[pos[I_DWIH1]];
    const float* dWhh1    = (const float*)d_in[pos[I_DWHH1]];
    const float* dbih1    = (const float*)d_in[pos[I_DBIH1]];
    const float* dbhh1    = (const float*)d_in[pos[I_DBHH1]];
    const float* proj_W   = (const float*)d_in[pos[I_PW]];
    const float* proj_b   = (const float*)d_in[pos[I_PB]];
    float* out = (float*)d_out;    // __output__ dtype: float32

    float* S = nullptr;
    cudaGetSymbolAddress((void**)&S, g_scratch);

    float* patch   = S + OFF_PATCH;
    float* c1      = S + OFF_C1;
    float* c2      = S + OFF_C2;
    float* xtbc    = S + OFF_XTBC;
    float* gif     = S + OFF_GIF;
    float* gib     = S + OFF_GIB;
    float* encout  = S + OFF_ENCOUT;
    float* encproj = S + OFF_ENCPROJ;
    float* hbuf    = S + OFF_HBUF;
    float* comb    = S + OFF_COMB;
    float* bridge  = S + OFF_BRIDGE;
    float* h0buf   = S + OFF_H0BUF;
    float* h1buf   = S + OFF_H1BUF;
    float* ctx     = S + OFF_CTX;
    float* logits  = S + OFF_LOGITS;
    int*   tok     = (int*)(S + OFF_TOK);

    // conv stack
    im2col1<<<cdiv(8192u * 1280u, 256u), 256>>>(features, patch);
    gemm(patch, conv_w1, conv_b1, c1, 8192, 512, 1280, 1);
    im2col2<<<cdiv(4096u * 2560u, 256u), 256>>>(c1, patch);
    gemm(patch, conv_w2, conv_b2, c2, 4096, 512, 2560, 1);
    xpose_bt<<<cdiv(4096u * 512u, 256u), 256>>>(c2, xtbc);

    // encoder input GEMMs (bih folded in)
    gemm(xtbc, Wih_f, bih_f, gif, 4096, 1536, 512, 0);
    gemm(xtbc, Wih_b, bih_b, gib, 4096, 1536, 512, 0);

    // encoder: h parity-0 zeroed, then 128 fused step launches
    cudaMemsetAsync(hbuf, 0, 32768 * sizeof(float));
    for (int t = 0; t < 128; t++)
        enc_step_k<<<32, 256>>>(gif, gib, Whh_f, Whh_b, bhh_f, bhh_b,
                                encout, hbuf, t);

    // bridge + attention precompute
    build_comb_k<<<cdiv(32u * 1024u, 256u), 256>>>(hbuf, comb);
    gemm(comb, bridge_W, bridge_b, bridge, 32, 1024, 1024, 0);
    split_bridge_k<<<cdiv(32u * 512u, 256u), 256>>>(bridge, h0buf, h1buf);
    gemm(encout, attn_We, nullptr, encproj, 4096, 512, 1024, 0);

    // decoder
    init_dec_k<<<1, 32>>>(tok, out);
    for (int s = 0; s < NSTEPS; s++) {
        int p = s & 1, q = 1 - p;
        dec_attn_k<<<32, 256>>>(encproj, encout, h1buf + p * 16384,
                                attn_Wd, attn_v, ctx);
        dec_gates0_k<<<32, 256>>>(emb, tok, ctx, h0buf + p * 16384,
                                  dWih0, dWhh0, dbih0, dbhh0, h0buf + q * 16384);
        dec_gates1_k<<<32, 256>>>(h0buf + q * 16384, h1buf + p * 16384,
                                  dWih1, dWhh1, dbih1, dbhh1, h1buf + q * 16384);
        dec_logits_k<<<125, 256>>>(h1buf + q * 16384, ctx, proj_W, proj_b, logits);
        argmax_k<<<32, 256>>>(logits, tok, out, s);
    }
}